// round 1
// baseline (speedup 1.0000x reference)
#include <cuda_runtime.h>
#include <math.h>

#define N_NODES 8192
#define DMODEL 1024
#define FINT 4096
#define KTOT 3072          // [agg0 | agg1 | x]
#define NEDGE 262144
#define LN_EPS 1e-6f

// ---------------- scratch (static device allocations; no cudaMalloc) -------
__device__ float g_A[(size_t)N_NODES * KTOT];     // 96 MB: rows = [agg0(1024) | agg1(1024) | x(1024)]
__device__ float g_mid[(size_t)N_NODES * FINT];   // 128 MB: relu(GEMM1 out)
__device__ int   g_cnt[2 * N_NODES];

// ---------------- zero agg region + counts --------------------------------
__global__ void zero_kernel() {
    size_t idx = (size_t)blockIdx.x * blockDim.x + threadIdx.x;
    size_t total = (size_t)N_NODES * 512;   // 2048 floats per node, as float4
    for (size_t i = idx; i < total; i += (size_t)gridDim.x * blockDim.x) {
        size_t n = i >> 9;          // /512
        size_t c = (i & 511) << 2;  // float4 within 2048 cols
        *(float4*)&g_A[n * KTOT + c] = make_float4(0.f, 0.f, 0.f, 0.f);
    }
    if (idx < 2 * N_NODES) g_cnt[idx] = 0;
}

// ---------------- LayerNorm: writes x into g_A[:, 2048:3072] --------------
__global__ __launch_bounds__(256) void ln_kernel(const float* __restrict__ hs,
                                                 const float* __restrict__ gamma,
                                                 const float* __restrict__ beta) {
    int n = blockIdx.x;
    int t = threadIdx.x;  // 256 threads, 4 floats each
    const float4 v = ((const float4*)(hs + (size_t)n * DMODEL))[t];
    float s  = v.x + v.y + v.z + v.w;
    float sq = v.x*v.x + v.y*v.y + v.z*v.z + v.w*v.w;

    __shared__ float red[16];
    // warp reduce
    for (int o = 16; o > 0; o >>= 1) {
        s  += __shfl_down_sync(0xffffffff, s,  o);
        sq += __shfl_down_sync(0xffffffff, sq, o);
    }
    int wid = t >> 5, lid = t & 31;
    if (lid == 0) { red[wid] = s; red[8 + wid] = sq; }
    __syncthreads();
    if (wid == 0) {
        s  = (lid < 8) ? red[lid]     : 0.f;
        sq = (lid < 8) ? red[8 + lid] : 0.f;
        for (int o = 4; o > 0; o >>= 1) {
            s  += __shfl_down_sync(0xffffffff, s,  o);
            sq += __shfl_down_sync(0xffffffff, sq, o);
        }
        if (lid == 0) { red[0] = s; red[1] = sq; }
    }
    __syncthreads();
    float mean = red[0] * (1.f / DMODEL);
    float var  = red[1] * (1.f / DMODEL) - mean * mean;
    float rstd = rsqrtf(var + LN_EPS);

    const float4 g = ((const float4*)gamma)[t];
    const float4 b = ((const float4*)beta)[t];
    float4 o;
    o.x = (v.x - mean) * rstd * g.x + b.x;
    o.y = (v.y - mean) * rstd * g.y + b.y;
    o.z = (v.z - mean) * rstd * g.z + b.z;
    o.w = (v.w - mean) * rstd * g.w + b.w;
    *(float4*)&g_A[(size_t)n * KTOT + 2048 + t * 4] = o;
}

// ---------------- edge degree counts ---------------------------------------
__global__ void count_kernel(const int* __restrict__ ei, const int* __restrict__ et) {
    int e = blockIdx.x * blockDim.x + threadIdx.x;
    if (e < NEDGE) {
        int dst = ei[NEDGE + e];
        int r   = et[e];
        atomicAdd(&g_cnt[r * N_NODES + dst], 1);
    }
}

// ---------------- scatter-add: one block per edge ---------------------------
__global__ __launch_bounds__(256) void scatter_kernel(const int* __restrict__ ei,
                                                      const int* __restrict__ et) {
    int e = blockIdx.x;
    int src = ei[e];
    int dst = ei[NEDGE + e];
    int r   = et[e];
    int d = threadIdx.x * 4;
    const float4 v = *(const float4*)&g_A[(size_t)src * KTOT + 2048 + d];
    float* p = &g_A[(size_t)dst * KTOT + r * 1024 + d];
    atomicAdd(p + 0, v.x);
    atomicAdd(p + 1, v.y);
    atomicAdd(p + 2, v.z);
    atomicAdd(p + 3, v.w);
}

// ---------------- divide by counts (mean) -----------------------------------
__global__ void mean_kernel() {
    size_t idx = (size_t)blockIdx.x * blockDim.x + threadIdx.x;
    size_t total = (size_t)N_NODES * 512;
    for (size_t i = idx; i < total; i += (size_t)gridDim.x * blockDim.x) {
        size_t n = i >> 9;
        size_t c = (i & 511) << 2;
        int r = (int)(c >> 10);
        int cnt = g_cnt[r * N_NODES + n];
        float sc = 1.f / (float)max(cnt, 1);
        float4* p = (float4*)&g_A[n * KTOT + c];
        float4 v = *p;
        v.x *= sc; v.y *= sc; v.z *= sc; v.w *= sc;
        *p = v;
    }
}

// ---------------- 128x128x8 SIMT fp32 GEMM ---------------------------------
// C[M,N] = A[M,K] @ B[K,N] (+ bias + relu | + residual)
// B row k comes from B0 if k < ksplit else B1 (row k-ksplit). Both ldb.
// mode 1: C = relu(acc + bias[col])       -> C (ldc = N)
// mode 2: C = acc + residual[row*ldc+col] -> C
__global__ __launch_bounds__(256) void gemm_kernel(
    const float* __restrict__ A, int lda, int K,
    const float* __restrict__ B0, const float* __restrict__ B1, int ksplit, int ldb,
    const float* __restrict__ bias, const float* __restrict__ residual,
    float* __restrict__ C, int ldc, int mode)
{
    __shared__ float As[8][128];
    __shared__ float Bs[8][128];
    const int tid = threadIdx.x;
    const int cRow = blockIdx.y, cCol = blockIdx.x;
    const int threadRow = tid >> 4;      // 0..15
    const int threadCol = tid & 15;      // 0..15
    const int innerRowA = tid >> 1;            // 0..127
    const int innerColA = (tid & 1) * 4;       // 0 or 4
    const int innerRowB = tid >> 5;            // 0..7
    const int innerColB = (tid & 31) * 4;      // 0..124

    const float* Abase = A + (size_t)cRow * 128 * lda;
    float acc[8][8];
    #pragma unroll
    for (int i = 0; i < 8; i++)
        #pragma unroll
        for (int j = 0; j < 8; j++) acc[i][j] = 0.f;

    for (int bk = 0; bk < K; bk += 8) {
        float4 a4 = *(const float4*)(Abase + (size_t)innerRowA * lda + bk + innerColA);
        As[innerColA + 0][innerRowA] = a4.x;
        As[innerColA + 1][innerRowA] = a4.y;
        As[innerColA + 2][innerRowA] = a4.z;
        As[innerColA + 3][innerRowA] = a4.w;

        int kg = bk + innerRowB;
        const float* brow = (kg < ksplit) ? (B0 + (size_t)kg * ldb)
                                          : (B1 + (size_t)(kg - ksplit) * ldb);
        *(float4*)&Bs[innerRowB][innerColB] =
            *(const float4*)(brow + (size_t)cCol * 128 + innerColB);
        __syncthreads();

        #pragma unroll
        for (int k = 0; k < 8; k++) {
            float ra[8], rb[8];
            *(float4*)&ra[0] = *(const float4*)&As[k][threadRow * 8];
            *(float4*)&ra[4] = *(const float4*)&As[k][threadRow * 8 + 4];
            *(float4*)&rb[0] = *(const float4*)&Bs[k][threadCol * 8];
            *(float4*)&rb[4] = *(const float4*)&Bs[k][threadCol * 8 + 4];
            #pragma unroll
            for (int i = 0; i < 8; i++)
                #pragma unroll
                for (int j = 0; j < 8; j++)
                    acc[i][j] = fmaf(ra[i], rb[j], acc[i][j]);
        }
        __syncthreads();
    }

    // epilogue
    #pragma unroll
    for (int i = 0; i < 8; i++) {
        int row = cRow * 128 + threadRow * 8 + i;
        #pragma unroll
        for (int jj = 0; jj < 2; jj++) {
            int col = cCol * 128 + threadCol * 8 + jj * 4;
            float4 v = *(float4*)&acc[i][jj * 4];
            if (mode == 1) {
                const float4 b = *(const float4*)(bias + col);
                v.x = fmaxf(v.x + b.x, 0.f);
                v.y = fmaxf(v.y + b.y, 0.f);
                v.z = fmaxf(v.z + b.z, 0.f);
                v.w = fmaxf(v.w + b.w, 0.f);
            } else {
                const float4 res = *(const float4*)(residual + (size_t)row * ldc + col);
                v.x += res.x; v.y += res.y; v.z += res.z; v.w += res.w;
            }
            *(float4*)(C + (size_t)row * ldc + col) = v;
        }
    }
}

// ---------------- launch -----------------------------------------------------
extern "C" void kernel_launch(void* const* d_in, const int* in_sizes, int n_in,
                              void* d_out, int out_size) {
    const float* hidden = (const float*)d_in[0];   // [8,1024,1024]
    const float* weight = (const float*)d_in[1];   // [2,1024,4096] contiguous
    const float* root   = (const float*)d_in[2];   // [1024,4096]
    const float* bias   = (const float*)d_in[3];   // [4096]
    const float* wo     = (const float*)d_in[4];   // [4096,1024]
    const float* gamma  = (const float*)d_in[5];   // [1024]
    const float* beta   = (const float*)d_in[6];   // [1024]
    const int*   ei     = (const int*)d_in[7];     // [2, 262144]
    const int*   et     = (const int*)d_in[8];     // [262144]
    float* out = (float*)d_out;

    float* gA;   cudaGetSymbolAddress((void**)&gA,   g_A);
    float* gMid; cudaGetSymbolAddress((void**)&gMid, g_mid);

    zero_kernel<<<4096, 256>>>();
    ln_kernel<<<N_NODES, 256>>>(hidden, gamma, beta);
    count_kernel<<<NEDGE / 256, 256>>>(ei, et);
    scatter_kernel<<<NEDGE, 256>>>(ei, et);
    mean_kernel<<<4096, 256>>>();

    // GEMM1: g_mid[8192,4096] = relu(g_A[8192,3072] @ [weight;root] + bias)
    gemm_kernel<<<dim3(FINT / 128, N_NODES / 128), 256>>>(
        gA, KTOT, KTOT,
        weight, root, 2048, FINT,
        bias, nullptr,
        gMid, FINT, 1);

    // GEMM2: out[8192,1024] = g_mid @ wo + hidden
    gemm_kernel<<<dim3(DMODEL / 128, N_NODES / 128), 256>>>(
        gMid, FINT, FINT,
        wo, wo, FINT, DMODEL,
        nullptr, hidden,
        out, DMODEL, 2);
}

// round 3
// speedup vs baseline: 2.8017x; 2.8017x over previous
#include <cuda_runtime.h>
#include <cuda_bf16.h>
#include <cstdint>
#include <math.h>

#define N_NODES 8192
#define DMODEL 1024
#define FINT 4096
#define KTOT 3072
#define NEDGE 262144
#define LN_EPS 1e-6f

// ---------------- PTX helpers (sm_80-era: valid on base compute_103) ---------
__device__ __forceinline__ uint32_t smem_u32(const void* p) {
    uint32_t a;
    asm("{ .reg .u64 t; cvta.to.shared.u64 t, %1; cvt.u32.u64 %0, t; }" : "=r"(a) : "l"(p));
    return a;
}
#define CP16(dst, src) asm volatile("cp.async.cg.shared.global [%0], [%1], 16;" :: "r"(dst), "l"(src))
#define CP_COMMIT()    asm volatile("cp.async.commit_group;" ::: "memory")
#define CP_WAIT1()     asm volatile("cp.async.wait_group 1;" ::: "memory")

__device__ __forceinline__ void ldsm4(uint32_t* r, uint32_t a) {
    asm volatile("ldmatrix.sync.aligned.m8n8.x4.shared.b16 {%0,%1,%2,%3}, [%4];"
                 : "=r"(r[0]), "=r"(r[1]), "=r"(r[2]), "=r"(r[3]) : "r"(a));
}
__device__ __forceinline__ void ldsm4t(uint32_t* r, uint32_t a) {
    asm volatile("ldmatrix.sync.aligned.m8n8.x4.trans.shared.b16 {%0,%1,%2,%3}, [%4];"
                 : "=r"(r[0]), "=r"(r[1]), "=r"(r[2]), "=r"(r[3]) : "r"(a));
}
__device__ __forceinline__ void mma16816(float* d, const uint32_t* a, const uint32_t* b) {
    asm volatile("mma.sync.aligned.m16n8k16.row.col.f32.bf16.bf16.f32 "
                 "{%0,%1,%2,%3}, {%4,%5,%6,%7}, {%8,%9}, {%0,%1,%2,%3};"
                 : "+f"(d[0]), "+f"(d[1]), "+f"(d[2]), "+f"(d[3])
                 : "r"(a[0]), "r"(a[1]), "r"(a[2]), "r"(a[3]), "r"(b[0]), "r"(b[1]));
}

// ---------------- scratch ----------------------------------------------------
__device__ float g_A[(size_t)N_NODES * KTOT];
__device__ __nv_bfloat16 g_Ahi[(size_t)N_NODES * KTOT];
__device__ __nv_bfloat16 g_Alo[(size_t)N_NODES * KTOT];
__device__ __nv_bfloat16 g_Bhi[(size_t)KTOT * FINT];
__device__ __nv_bfloat16 g_Blo[(size_t)KTOT * FINT];
__device__ __nv_bfloat16 g_Whi[(size_t)FINT * DMODEL];
__device__ __nv_bfloat16 g_Wlo[(size_t)FINT * DMODEL];
__device__ __nv_bfloat16 g_Mhi[(size_t)N_NODES * FINT];
__device__ __nv_bfloat16 g_Mlo[(size_t)N_NODES * FINT];
__device__ int g_cnt[2 * N_NODES];

// ---------------- small kernels ----------------------------------------------
__global__ void zero_kernel() {
    size_t idx = (size_t)blockIdx.x * blockDim.x + threadIdx.x;
    size_t total = (size_t)N_NODES * 512;
    for (size_t i = idx; i < total; i += (size_t)gridDim.x * blockDim.x) {
        size_t n = i >> 9;
        size_t c = (i & 511) << 2;
        *(float4*)&g_A[n * KTOT + c] = make_float4(0.f, 0.f, 0.f, 0.f);
    }
    if (idx < 2 * N_NODES) g_cnt[idx] = 0;
}

__global__ __launch_bounds__(256) void ln_kernel(const float* __restrict__ hs,
                                                 const float* __restrict__ gamma,
                                                 const float* __restrict__ beta) {
    int n = blockIdx.x;
    int t = threadIdx.x;
    const float4 v = ((const float4*)(hs + (size_t)n * DMODEL))[t];
    float s  = v.x + v.y + v.z + v.w;
    float sq = v.x * v.x + v.y * v.y + v.z * v.z + v.w * v.w;
    __shared__ float red[16];
    for (int o = 16; o > 0; o >>= 1) {
        s  += __shfl_down_sync(0xffffffff, s,  o);
        sq += __shfl_down_sync(0xffffffff, sq, o);
    }
    int wid = t >> 5, lid = t & 31;
    if (lid == 0) { red[wid] = s; red[8 + wid] = sq; }
    __syncthreads();
    if (wid == 0) {
        s  = (lid < 8) ? red[lid]     : 0.f;
        sq = (lid < 8) ? red[8 + lid] : 0.f;
        for (int o = 4; o > 0; o >>= 1) {
            s  += __shfl_down_sync(0xffffffff, s,  o);
            sq += __shfl_down_sync(0xffffffff, sq, o);
        }
        if (lid == 0) { red[0] = s; red[1] = sq; }
    }
    __syncthreads();
    float mean = red[0] * (1.f / DMODEL);
    float var  = red[1] * (1.f / DMODEL) - mean * mean;
    float rstd = rsqrtf(var + LN_EPS);
    const float4 g = ((const float4*)gamma)[t];
    const float4 b = ((const float4*)beta)[t];
    float4 o;
    o.x = (v.x - mean) * rstd * g.x + b.x;
    o.y = (v.y - mean) * rstd * g.y + b.y;
    o.z = (v.z - mean) * rstd * g.z + b.z;
    o.w = (v.w - mean) * rstd * g.w + b.w;
    *(float4*)&g_A[(size_t)n * KTOT + 2048 + t * 4] = o;
}

__global__ void count_kernel(const int* __restrict__ ei, const int* __restrict__ et) {
    int e = blockIdx.x * blockDim.x + threadIdx.x;
    if (e < NEDGE) atomicAdd(&g_cnt[et[e] * N_NODES + ei[NEDGE + e]], 1);
}

__global__ __launch_bounds__(256) void scatter_kernel(const int* __restrict__ ei,
                                                      const int* __restrict__ et) {
    int e = blockIdx.x;
    int src = ei[e];
    int dst = ei[NEDGE + e];
    int r   = et[e];
    int d = threadIdx.x * 4;
    const float4 v = *(const float4*)&g_A[(size_t)src * KTOT + 2048 + d];
    float* p = &g_A[(size_t)dst * KTOT + r * 1024 + d];
    atomicAdd(p + 0, v.x);
    atomicAdd(p + 1, v.y);
    atomicAdd(p + 2, v.z);
    atomicAdd(p + 3, v.w);
}

__global__ void mean_kernel() {
    size_t idx = (size_t)blockIdx.x * blockDim.x + threadIdx.x;
    size_t total = (size_t)N_NODES * 512;
    for (size_t i = idx; i < total; i += (size_t)gridDim.x * blockDim.x) {
        size_t n = i >> 9;
        size_t c = (i & 511) << 2;
        int r = (int)(c >> 10);
        int cnt = g_cnt[r * N_NODES + n];
        float sc = 1.f / (float)max(cnt, 1);
        float4* p = (float4*)&g_A[n * KTOT + c];
        float4 v = *p;
        v.x *= sc; v.y *= sc; v.z *= sc; v.w *= sc;
        *p = v;
    }
}

__global__ void split_kernel(const float* __restrict__ src,
                             __nv_bfloat16* __restrict__ hi,
                             __nv_bfloat16* __restrict__ lo, size_t n4) {
    size_t i = (size_t)blockIdx.x * blockDim.x + threadIdx.x;
    for (; i < n4; i += (size_t)gridDim.x * blockDim.x) {
        float4 v = ((const float4*)src)[i];
        __nv_bfloat16 h0 = __float2bfloat16(v.x), h1 = __float2bfloat16(v.y),
                      h2 = __float2bfloat16(v.z), h3 = __float2bfloat16(v.w);
        __nv_bfloat16 l0 = __float2bfloat16(v.x - __bfloat162float(h0));
        __nv_bfloat16 l1 = __float2bfloat16(v.y - __bfloat162float(h1));
        __nv_bfloat16 l2 = __float2bfloat16(v.z - __bfloat162float(h2));
        __nv_bfloat16 l3 = __float2bfloat16(v.w - __bfloat162float(h3));
        ushort4 hv = { *(unsigned short*)&h0, *(unsigned short*)&h1,
                       *(unsigned short*)&h2, *(unsigned short*)&h3 };
        ushort4 lv = { *(unsigned short*)&l0, *(unsigned short*)&l1,
                       *(unsigned short*)&l2, *(unsigned short*)&l3 };
        ((ushort4*)hi)[i] = hv;
        ((ushort4*)lo)[i] = lv;
    }
}

// ---------------- mma.sync split-bf16 GEMM ------------------------------------
// C tile 128x128 per CTA. A [M,K] K-major bf16 hi/lo. B [K,N] N-major bf16 hi/lo.
// acc += Ahi*Bhi + Ahi*Blo + Alo*Bhi (fp32 accumulate).
// mode 1: relu(acc+bias) -> bf16 hi/lo (outHi/outLo, ld=ldB)
// mode 2: acc + residual -> fp32 (outF, ld=ldB)
#define STAGE_BYTES 65536
#define OFF_ALO 16384
#define OFF_BHI 32768
#define SMEM_DYN (2 * STAGE_BYTES)

__device__ __forceinline__ uint32_t a_off(int row, int q) {
    return (uint32_t)(row * 128 + ((q ^ (row & 7)) << 4));
}
__device__ __forceinline__ uint32_t b_off(int row, int q) {
    return (uint32_t)(row * 256 + (((q & 8) | ((q & 7) ^ (row & 7))) << 4));
}

__global__ __launch_bounds__(256) void gemm_mma(
    const __nv_bfloat16* __restrict__ Ahi, const __nv_bfloat16* __restrict__ Alo,
    int ldA, int K,
    const __nv_bfloat16* __restrict__ Bhi, const __nv_bfloat16* __restrict__ Blo,
    int ldB,
    const float* __restrict__ bias, const float* __restrict__ residual,
    float* __restrict__ outF,
    __nv_bfloat16* __restrict__ outHi, __nv_bfloat16* __restrict__ outLo,
    int mode)
{
    extern __shared__ __align__(1024) char smem[];
    const uint32_t sb = smem_u32(smem);
    const int tid = threadIdx.x, wid = tid >> 5, lane = tid & 31;
    const int rowBase = blockIdx.y * 128;
    const int nBase   = blockIdx.x * 128;
    const int warp_m = (wid >> 2) * 64;
    const int warp_n = (wid & 3) * 32;
    const int lr = lane & 15, lc = lane >> 4;
    const int nchunk = K >> 6;

    float acc[4][4][4];
    #pragma unroll
    for (int i = 0; i < 4; i++)
        #pragma unroll
        for (int j = 0; j < 4; j++)
            #pragma unroll
            for (int k = 0; k < 4; k++) acc[i][j][k] = 0.f;

    auto load_chunk = [&](int c, int s) {
        const uint32_t sbase = sb + s * STAGE_BYTES;
        const int kb = c * 64;
        #pragma unroll
        for (int i = 0; i < 4; i++) {
            int v = tid + i * 256;
            int row = v >> 3, q = v & 7;
            uint32_t so = sbase + a_off(row, q);
            size_t g = (size_t)(rowBase + row) * ldA + kb + q * 8;
            CP16(so, Ahi + g);
            CP16(so + OFF_ALO, Alo + g);
        }
        #pragma unroll
        for (int i = 0; i < 4; i++) {
            int v = tid + i * 256;
            int row = v >> 4, q = v & 15;
            uint32_t so = sbase + OFF_BHI + b_off(row, q);
            size_t g = (size_t)(kb + row) * ldB + nBase + q * 8;
            CP16(so, Bhi + g);
            CP16(so + OFF_ALO, Blo + g);   // OFF_BLO - OFF_BHI == 16384
        }
    };

    load_chunk(0, 0); CP_COMMIT();
    load_chunk(1, 1); CP_COMMIT();

    for (int c = 0; c < nchunk; c++) {
        CP_WAIT1();
        __syncthreads();
        const uint32_t base = sb + (c & 1) * STAGE_BYTES;
        #pragma unroll
        for (int ks = 0; ks < 4; ks++) {
            uint32_t ah[4][4], al[4][4];
            #pragma unroll
            for (int mi = 0; mi < 4; mi++) {
                int row = warp_m + mi * 16 + lr;
                int q = ks * 2 + lc;
                uint32_t addr = base + a_off(row, q);
                ldsm4(ah[mi], addr);
                ldsm4(al[mi], addr + OFF_ALO);
            }
            uint32_t bh[4][2], bl[4][2];
            #pragma unroll
            for (int np = 0; np < 2; np++) {
                int row = ks * 16 + lr;
                int q = (warp_n >> 3) + np * 2 + lc;
                uint32_t addr = base + OFF_BHI + b_off(row, q);
                uint32_t t[4];
                ldsm4t(t, addr);
                bh[np * 2][0] = t[0]; bh[np * 2][1] = t[1];
                bh[np * 2 + 1][0] = t[2]; bh[np * 2 + 1][1] = t[3];
                ldsm4t(t, addr + OFF_ALO);
                bl[np * 2][0] = t[0]; bl[np * 2][1] = t[1];
                bl[np * 2 + 1][0] = t[2]; bl[np * 2 + 1][1] = t[3];
            }
            #pragma unroll
            for (int mi = 0; mi < 4; mi++)
                #pragma unroll
                for (int ni = 0; ni < 4; ni++) {
                    mma16816(acc[mi][ni], ah[mi], bh[ni]);
                    mma16816(acc[mi][ni], ah[mi], bl[ni]);
                    mma16816(acc[mi][ni], al[mi], bh[ni]);
                }
        }
        __syncthreads();
        if (c + 2 < nchunk) load_chunk(c + 2, c & 1);
        CP_COMMIT();
    }

    // epilogue straight from registers
    #pragma unroll
    for (int mi = 0; mi < 4; mi++) {
        #pragma unroll
        for (int ni = 0; ni < 4; ni++) {
            int r0 = rowBase + warp_m + mi * 16 + (lane >> 2);
            int col = nBase + warp_n + ni * 8 + (lane & 3) * 2;
            #pragma unroll
            for (int h = 0; h < 2; h++) {
                int row = r0 + h * 8;
                float x0 = acc[mi][ni][h * 2 + 0];
                float x1 = acc[mi][ni][h * 2 + 1];
                size_t go = (size_t)row * ldB + col;
                if (mode == 1) {
                    x0 = fmaxf(x0 + bias[col], 0.f);
                    x1 = fmaxf(x1 + bias[col + 1], 0.f);
                    __nv_bfloat16 h0 = __float2bfloat16(x0);
                    __nv_bfloat16 h1 = __float2bfloat16(x1);
                    __nv_bfloat16 l0 = __float2bfloat16(x0 - __bfloat162float(h0));
                    __nv_bfloat16 l1 = __float2bfloat16(x1 - __bfloat162float(h1));
                    ushort2 hv = { *(unsigned short*)&h0, *(unsigned short*)&h1 };
                    ushort2 lv = { *(unsigned short*)&l0, *(unsigned short*)&l1 };
                    *(ushort2*)&outHi[go] = hv;
                    *(ushort2*)&outLo[go] = lv;
                } else {
                    float2 res = *(const float2*)&residual[go];
                    float2 y = { x0 + res.x, x1 + res.y };
                    *(float2*)&outF[go] = y;
                }
            }
        }
    }
}

// ---------------- launch -------------------------------------------------------
extern "C" void kernel_launch(void* const* d_in, const int* in_sizes, int n_in,
                              void* d_out, int out_size) {
    const float* hidden = (const float*)d_in[0];
    const float* weight = (const float*)d_in[1];
    const float* root   = (const float*)d_in[2];
    const float* bias   = (const float*)d_in[3];
    const float* wo     = (const float*)d_in[4];
    const float* gamma  = (const float*)d_in[5];
    const float* beta   = (const float*)d_in[6];
    const int*   ei     = (const int*)d_in[7];
    const int*   et     = (const int*)d_in[8];
    float* out = (float*)d_out;

    float* gA;
    cudaGetSymbolAddress((void**)&gA, g_A);
    __nv_bfloat16 *gAhi, *gAlo, *gBhi, *gBlo, *gWhi, *gWlo, *gMhi, *gMlo;
    cudaGetSymbolAddress((void**)&gAhi, g_Ahi);
    cudaGetSymbolAddress((void**)&gAlo, g_Alo);
    cudaGetSymbolAddress((void**)&gBhi, g_Bhi);
    cudaGetSymbolAddress((void**)&gBlo, g_Blo);
    cudaGetSymbolAddress((void**)&gWhi, g_Whi);
    cudaGetSymbolAddress((void**)&gWlo, g_Wlo);
    cudaGetSymbolAddress((void**)&gMhi, g_Mhi);
    cudaGetSymbolAddress((void**)&gMlo, g_Mlo);

    cudaFuncSetAttribute(gemm_mma, cudaFuncAttributeMaxDynamicSharedMemorySize, SMEM_DYN);

    zero_kernel<<<4096, 256>>>();
    ln_kernel<<<N_NODES, 256>>>(hidden, gamma, beta);
    count_kernel<<<NEDGE / 256, 256>>>(ei, et);
    scatter_kernel<<<NEDGE, 256>>>(ei, et);
    mean_kernel<<<4096, 256>>>();

    split_kernel<<<2048, 256>>>(weight, gBhi, gBlo, (size_t)2048 * FINT / 4);
    split_kernel<<<1024, 256>>>(root, gBhi + (size_t)2048 * FINT, gBlo + (size_t)2048 * FINT,
                                (size_t)1024 * FINT / 4);
    split_kernel<<<1024, 256>>>(wo, gWhi, gWlo, (size_t)FINT * DMODEL / 4);
    split_kernel<<<8192, 256>>>(gA, gAhi, gAlo, (size_t)N_NODES * KTOT / 4);

    // GEMM1: mid = relu(A[8192,3072] @ [weight;root][3072,4096] + bias) -> bf16 hi/lo
    gemm_mma<<<dim3(FINT / 128, N_NODES / 128), 256, SMEM_DYN>>>(
        gAhi, gAlo, KTOT, KTOT,
        gBhi, gBlo, FINT,
        bias, nullptr,
        nullptr, gMhi, gMlo, 1);

    // GEMM2: out = mid[8192,4096] @ wo[4096,1024] + hidden -> fp32
    gemm_mma<<<dim3(DMODEL / 128, N_NODES / 128), 256, SMEM_DYN>>>(
        gMhi, gMlo, FINT, FINT,
        gWhi, gWlo, DMODEL,
        nullptr, hidden,
        out, nullptr, nullptr, 2);
}

// round 4
// speedup vs baseline: 3.5373x; 1.2626x over previous
#include <cuda_runtime.h>
#include <cuda_bf16.h>
#include <cstdint>
#include <math.h>

#define N_NODES 8192
#define DMODEL 1024
#define FINT 4096
#define KTOT 3072
#define NEDGE 262144
#define NKEY (2 * N_NODES)
#define LN_EPS 1e-6f

// ---------------- PTX helpers (sm_80-era: valid on base compute_103) ---------
__device__ __forceinline__ uint32_t smem_u32(const void* p) {
    uint32_t a;
    asm("{ .reg .u64 t; cvta.to.shared.u64 t, %1; cvt.u32.u64 %0, t; }" : "=r"(a) : "l"(p));
    return a;
}
#define CP16(dst, src) asm volatile("cp.async.cg.shared.global [%0], [%1], 16;" :: "r"(dst), "l"(src))
#define CP_COMMIT()    asm volatile("cp.async.commit_group;" ::: "memory")
#define CP_WAIT1()     asm volatile("cp.async.wait_group 1;" ::: "memory")

__device__ __forceinline__ void ldsm4(uint32_t* r, uint32_t a) {
    asm volatile("ldmatrix.sync.aligned.m8n8.x4.shared.b16 {%0,%1,%2,%3}, [%4];"
                 : "=r"(r[0]), "=r"(r[1]), "=r"(r[2]), "=r"(r[3]) : "r"(a));
}
__device__ __forceinline__ void ldsm4t(uint32_t* r, uint32_t a) {
    asm volatile("ldmatrix.sync.aligned.m8n8.x4.trans.shared.b16 {%0,%1,%2,%3}, [%4];"
                 : "=r"(r[0]), "=r"(r[1]), "=r"(r[2]), "=r"(r[3]) : "r"(a));
}
__device__ __forceinline__ void mma16816(float* d, const uint32_t* a, const uint32_t* b) {
    asm volatile("mma.sync.aligned.m16n8k16.row.col.f32.bf16.bf16.f32 "
                 "{%0,%1,%2,%3}, {%4,%5,%6,%7}, {%8,%9}, {%0,%1,%2,%3};"
                 : "+f"(d[0]), "+f"(d[1]), "+f"(d[2]), "+f"(d[3])
                 : "r"(a[0]), "r"(a[1]), "r"(a[2]), "r"(a[3]), "r"(b[0]), "r"(b[1]));
}

// ---------------- scratch ----------------------------------------------------
__device__ float g_x[(size_t)N_NODES * DMODEL];          // LN output, compact fp32
__device__ __nv_bfloat16 g_Ahi[(size_t)N_NODES * KTOT];
__device__ __nv_bfloat16 g_Alo[(size_t)N_NODES * KTOT];
__device__ __nv_bfloat16 g_Bhi[(size_t)KTOT * FINT];
__device__ __nv_bfloat16 g_Blo[(size_t)KTOT * FINT];
__device__ __nv_bfloat16 g_Whi[(size_t)FINT * DMODEL];
__device__ __nv_bfloat16 g_Wlo[(size_t)FINT * DMODEL];
__device__ __nv_bfloat16 g_Mhi[(size_t)N_NODES * FINT];
__device__ __nv_bfloat16 g_Mlo[(size_t)N_NODES * FINT];
__device__ int g_cnt[NKEY];
__device__ int g_off[NKEY];
__device__ int g_cur[NKEY];
__device__ int g_srcbuf[NEDGE];

// ---------------- helpers ------------------------------------------------------
__device__ __forceinline__ void split2(float x0, float x1, ushort2& hv, ushort2& lv) {
    __nv_bfloat16 h0 = __float2bfloat16(x0);
    __nv_bfloat16 h1 = __float2bfloat16(x1);
    __nv_bfloat16 l0 = __float2bfloat16(x0 - __bfloat162float(h0));
    __nv_bfloat16 l1 = __float2bfloat16(x1 - __bfloat162float(h1));
    hv.x = *(unsigned short*)&h0; hv.y = *(unsigned short*)&h1;
    lv.x = *(unsigned short*)&l0; lv.y = *(unsigned short*)&l1;
}
__device__ __forceinline__ void split4(const float4& v, ushort4& hv, ushort4& lv) {
    ushort2 h01, l01, h23, l23;
    split2(v.x, v.y, h01, l01);
    split2(v.z, v.w, h23, l23);
    hv.x = h01.x; hv.y = h01.y; hv.z = h23.x; hv.w = h23.y;
    lv.x = l01.x; lv.y = l01.y; lv.z = l23.x; lv.w = l23.y;
}

// ---------------- pipeline kernels ---------------------------------------------
__global__ void zero_cnt_kernel() {
    int i = blockIdx.x * blockDim.x + threadIdx.x;
    if (i < NKEY) g_cnt[i] = 0;
}

// LN: hidden -> g_x (fp32 compact) + hi/lo x part of A (cols 2048..3071)
__global__ __launch_bounds__(256) void ln_kernel(const float* __restrict__ hs,
                                                 const float* __restrict__ gamma,
                                                 const float* __restrict__ beta) {
    int n = blockIdx.x;
    int t = threadIdx.x;
    const float4 v = ((const float4*)(hs + (size_t)n * DMODEL))[t];
    float s  = v.x + v.y + v.z + v.w;
    float sq = v.x * v.x + v.y * v.y + v.z * v.z + v.w * v.w;
    __shared__ float red[16];
    for (int o = 16; o > 0; o >>= 1) {
        s  += __shfl_down_sync(0xffffffff, s,  o);
        sq += __shfl_down_sync(0xffffffff, sq, o);
    }
    int wid = t >> 5, lid = t & 31;
    if (lid == 0) { red[wid] = s; red[8 + wid] = sq; }
    __syncthreads();
    if (wid == 0) {
        s  = (lid < 8) ? red[lid]     : 0.f;
        sq = (lid < 8) ? red[8 + lid] : 0.f;
        for (int o = 4; o > 0; o >>= 1) {
            s  += __shfl_down_sync(0xffffffff, s,  o);
            sq += __shfl_down_sync(0xffffffff, sq, o);
        }
        if (lid == 0) { red[0] = s; red[1] = sq; }
    }
    __syncthreads();
    float mean = red[0] * (1.f / DMODEL);
    float var  = red[1] * (1.f / DMODEL) - mean * mean;
    float rstd = rsqrtf(var + LN_EPS);
    const float4 g = ((const float4*)gamma)[t];
    const float4 b = ((const float4*)beta)[t];
    float4 o;
    o.x = (v.x - mean) * rstd * g.x + b.x;
    o.y = (v.y - mean) * rstd * g.y + b.y;
    o.z = (v.z - mean) * rstd * g.z + b.z;
    o.w = (v.w - mean) * rstd * g.w + b.w;
    *(float4*)&g_x[(size_t)n * DMODEL + t * 4] = o;
    ushort4 hv, lv;
    split4(o, hv, lv);
    size_t a = ((size_t)n * KTOT + 2048) / 4 + t;
    ((ushort4*)g_Ahi)[a] = hv;
    ((ushort4*)g_Alo)[a] = lv;
}

__global__ void count_kernel(const int* __restrict__ ei, const int* __restrict__ et) {
    int e = blockIdx.x * blockDim.x + threadIdx.x;
    if (e < NEDGE) atomicAdd(&g_cnt[et[e] * N_NODES + ei[NEDGE + e]], 1);
}

// single-block exclusive scan over 16384 counts -> g_off, g_cur
__global__ __launch_bounds__(1024) void scan_kernel() {
    int tid = threadIdx.x;
    int base = tid * 16;
    int loc[16];
    int s = 0;
    #pragma unroll
    for (int i = 0; i < 16; i++) { loc[i] = s; s += g_cnt[base + i]; }
    __shared__ int ps[1024];
    int mine = s;
    ps[tid] = s;
    __syncthreads();
    for (int off = 1; off < 1024; off <<= 1) {
        int v = (tid >= off) ? ps[tid - off] : 0;
        __syncthreads();
        ps[tid] += v;
        __syncthreads();
    }
    int ex = ps[tid] - mine;
    #pragma unroll
    for (int i = 0; i < 16; i++) {
        int o = ex + loc[i];
        g_off[base + i] = o;
        g_cur[base + i] = o;
    }
}

__global__ void bucket_kernel(const int* __restrict__ ei, const int* __restrict__ et) {
    int e = blockIdx.x * blockDim.x + threadIdx.x;
    if (e < NEDGE) {
        int key = et[e] * N_NODES + ei[NEDGE + e];
        int pos = atomicAdd(&g_cur[key], 1);
        g_srcbuf[pos] = ei[e];
    }
}

// one CTA per (rel,dst): mean-aggregate src rows, emit bf16 hi/lo into A
__global__ __launch_bounds__(256) void gather_kernel() {
    int key = blockIdx.x;
    int node = key & (N_NODES - 1);
    int r = key >> 13;
    int off = g_off[key];
    int cnt = g_cnt[key];
    int c = threadIdx.x * 4;

    float4 acc = make_float4(0.f, 0.f, 0.f, 0.f);
    int i = 0;
    for (; i + 2 <= cnt; i += 2) {
        int s0 = g_srcbuf[off + i];
        int s1 = g_srcbuf[off + i + 1];
        float4 v0 = *(const float4*)&g_x[(size_t)s0 * DMODEL + c];
        float4 v1 = *(const float4*)&g_x[(size_t)s1 * DMODEL + c];
        acc.x += v0.x + v1.x;
        acc.y += v0.y + v1.y;
        acc.z += v0.z + v1.z;
        acc.w += v0.w + v1.w;
    }
    if (i < cnt) {
        int s0 = g_srcbuf[off + i];
        float4 v0 = *(const float4*)&g_x[(size_t)s0 * DMODEL + c];
        acc.x += v0.x; acc.y += v0.y; acc.z += v0.z; acc.w += v0.w;
    }
    float sc = 1.f / (float)max(cnt, 1);
    acc.x *= sc; acc.y *= sc; acc.z *= sc; acc.w *= sc;
    ushort4 hv, lv;
    split4(acc, hv, lv);
    size_t a = ((size_t)node * KTOT + (size_t)r * 1024 + c) >> 2;
    ((ushort4*)g_Ahi)[a] = hv;
    ((ushort4*)g_Alo)[a] = lv;
}

__global__ void split_kernel(const float* __restrict__ src,
                             __nv_bfloat16* __restrict__ hi,
                             __nv_bfloat16* __restrict__ lo, size_t n4) {
    size_t i = (size_t)blockIdx.x * blockDim.x + threadIdx.x;
    for (; i < n4; i += (size_t)gridDim.x * blockDim.x) {
        float4 v = ((const float4*)src)[i];
        ushort4 hv, lv;
        split4(v, hv, lv);
        ((ushort4*)hi)[i] = hv;
        ((ushort4*)lo)[i] = lv;
    }
}

// ---------------- mma.sync split-bf16 GEMM ------------------------------------
#define STAGE_BYTES 65536
#define OFF_ALO 16384
#define OFF_BHI 32768
#define SMEM_DYN (2 * STAGE_BYTES)

__device__ __forceinline__ uint32_t a_off(int row, int q) {
    return (uint32_t)(row * 128 + ((q ^ (row & 7)) << 4));
}
__device__ __forceinline__ uint32_t b_off(int row, int q) {
    return (uint32_t)(row * 256 + (((q & 8) | ((q & 7) ^ (row & 7))) << 4));
}

__global__ __launch_bounds__(256) void gemm_mma(
    const __nv_bfloat16* __restrict__ Ahi, const __nv_bfloat16* __restrict__ Alo,
    int ldA, int K,
    const __nv_bfloat16* __restrict__ Bhi, const __nv_bfloat16* __restrict__ Blo,
    int ldB,
    const float* __restrict__ bias, const float* __restrict__ residual,
    float* __restrict__ outF,
    __nv_bfloat16* __restrict__ outHi, __nv_bfloat16* __restrict__ outLo,
    int mode)
{
    extern __shared__ __align__(1024) char smem[];
    const uint32_t sb = smem_u32(smem);
    const int tid = threadIdx.x, wid = tid >> 5, lane = tid & 31;
    const int rowBase = blockIdx.y * 128;
    const int nBase   = blockIdx.x * 128;
    const int warp_m = (wid >> 2) * 64;
    const int warp_n = (wid & 3) * 32;
    const int lr = lane & 15, lc = lane >> 4;
    const int nchunk = K >> 6;

    float acc[4][4][4];
    #pragma unroll
    for (int i = 0; i < 4; i++)
        #pragma unroll
        for (int j = 0; j < 4; j++)
            #pragma unroll
            for (int k = 0; k < 4; k++) acc[i][j][k] = 0.f;

    auto load_chunk = [&](int c, int s) {
        const uint32_t sbase = sb + s * STAGE_BYTES;
        const int kb = c * 64;
        #pragma unroll
        for (int i = 0; i < 4; i++) {
            int v = tid + i * 256;
            int row = v >> 3, q = v & 7;
            uint32_t so = sbase + a_off(row, q);
            size_t g = (size_t)(rowBase + row) * ldA + kb + q * 8;
            CP16(so, Ahi + g);
            CP16(so + OFF_ALO, Alo + g);
        }
        #pragma unroll
        for (int i = 0; i < 4; i++) {
            int v = tid + i * 256;
            int row = v >> 4, q = v & 15;
            uint32_t so = sbase + OFF_BHI + b_off(row, q);
            size_t g = (size_t)(kb + row) * ldB + nBase + q * 8;
            CP16(so, Bhi + g);
            CP16(so + OFF_ALO, Blo + g);
        }
    };

    load_chunk(0, 0); CP_COMMIT();
    load_chunk(1, 1); CP_COMMIT();

    for (int c = 0; c < nchunk; c++) {
        CP_WAIT1();
        __syncthreads();
        const uint32_t base = sb + (c & 1) * STAGE_BYTES;
        #pragma unroll
        for (int ks = 0; ks < 4; ks++) {
            uint32_t ah[4][4], al[4][4];
            #pragma unroll
            for (int mi = 0; mi < 4; mi++) {
                int row = warp_m + mi * 16 + lr;
                int q = ks * 2 + lc;
                uint32_t addr = base + a_off(row, q);
                ldsm4(ah[mi], addr);
                ldsm4(al[mi], addr + OFF_ALO);
            }
            uint32_t bh[4][2], bl[4][2];
            #pragma unroll
            for (int np = 0; np < 2; np++) {
                int row = ks * 16 + lr;
                int q = (warp_n >> 3) + np * 2 + lc;
                uint32_t addr = base + OFF_BHI + b_off(row, q);
                uint32_t t[4];
                ldsm4t(t, addr);
                bh[np * 2][0] = t[0]; bh[np * 2][1] = t[1];
                bh[np * 2 + 1][0] = t[2]; bh[np * 2 + 1][1] = t[3];
                ldsm4t(t, addr + OFF_ALO);
                bl[np * 2][0] = t[0]; bl[np * 2][1] = t[1];
                bl[np * 2 + 1][0] = t[2]; bl[np * 2 + 1][1] = t[3];
            }
            #pragma unroll
            for (int mi = 0; mi < 4; mi++)
                #pragma unroll
                for (int ni = 0; ni < 4; ni++) {
                    mma16816(acc[mi][ni], ah[mi], bh[ni]);
                    mma16816(acc[mi][ni], ah[mi], bl[ni]);
                    mma16816(acc[mi][ni], al[mi], bh[ni]);
                }
        }
        __syncthreads();
        if (c + 2 < nchunk) load_chunk(c + 2, c & 1);
        CP_COMMIT();
    }

    #pragma unroll
    for (int mi = 0; mi < 4; mi++) {
        #pragma unroll
        for (int ni = 0; ni < 4; ni++) {
            int r0 = rowBase + warp_m + mi * 16 + (lane >> 2);
            int col = nBase + warp_n + ni * 8 + (lane & 3) * 2;
            #pragma unroll
            for (int h = 0; h < 2; h++) {
                int row = r0 + h * 8;
                float x0 = acc[mi][ni][h * 2 + 0];
                float x1 = acc[mi][ni][h * 2 + 1];
                size_t go = (size_t)row * ldB + col;
                if (mode == 1) {
                    x0 = fmaxf(x0 + bias[col], 0.f);
                    x1 = fmaxf(x1 + bias[col + 1], 0.f);
                    ushort2 hv, lv;
                    split2(x0, x1, hv, lv);
                    *(ushort2*)&outHi[go] = hv;
                    *(ushort2*)&outLo[go] = lv;
                } else {
                    float2 res = *(const float2*)&residual[go];
                    float2 y = { x0 + res.x, x1 + res.y };
                    *(float2*)&outF[go] = y;
                }
            }
        }
    }
}

// ---------------- launch -------------------------------------------------------
extern "C" void kernel_launch(void* const* d_in, const int* in_sizes, int n_in,
                              void* d_out, int out_size) {
    const float* hidden = (const float*)d_in[0];
    const float* weight = (const float*)d_in[1];
    const float* root   = (const float*)d_in[2];
    const float* bias   = (const float*)d_in[3];
    const float* wo     = (const float*)d_in[4];
    const float* gamma  = (const float*)d_in[5];
    const float* beta   = (const float*)d_in[6];
    const int*   ei     = (const int*)d_in[7];
    const int*   et     = (const int*)d_in[8];
    float* out = (float*)d_out;

    __nv_bfloat16 *gAhi, *gAlo, *gBhi, *gBlo, *gWhi, *gWlo, *gMhi, *gMlo;
    cudaGetSymbolAddress((void**)&gAhi, g_Ahi);
    cudaGetSymbolAddress((void**)&gAlo, g_Alo);
    cudaGetSymbolAddress((void**)&gBhi, g_Bhi);
    cudaGetSymbolAddress((void**)&gBlo, g_Blo);
    cudaGetSymbolAddress((void**)&gWhi, g_Whi);
    cudaGetSymbolAddress((void**)&gWlo, g_Wlo);
    cudaGetSymbolAddress((void**)&gMhi, g_Mhi);
    cudaGetSymbolAddress((void**)&gMlo, g_Mlo);

    cudaFuncSetAttribute(gemm_mma, cudaFuncAttributeMaxDynamicSharedMemorySize, SMEM_DYN);

    zero_cnt_kernel<<<NKEY / 256, 256>>>();
    ln_kernel<<<N_NODES, 256>>>(hidden, gamma, beta);
    count_kernel<<<NEDGE / 256, 256>>>(ei, et);
    scan_kernel<<<1, 1024>>>();
    bucket_kernel<<<NEDGE / 256, 256>>>(ei, et);
    gather_kernel<<<NKEY, 256>>>();

    split_kernel<<<2048, 256>>>(weight, gBhi, gBlo, (size_t)2048 * FINT / 4);
    split_kernel<<<1024, 256>>>(root, gBhi + (size_t)2048 * FINT, gBlo + (size_t)2048 * FINT,
                                (size_t)1024 * FINT / 4);
    split_kernel<<<1024, 256>>>(wo, gWhi, gWlo, (size_t)FINT * DMODEL / 4);

    // GEMM1: mid = relu(A[8192,3072] @ [weight;root][3072,4096] + bias) -> bf16 hi/lo
    gemm_mma<<<dim3(FINT / 128, N_NODES / 128), 256, SMEM_DYN>>>(
        gAhi, gAlo, KTOT, KTOT,
        gBhi, gBlo, FINT,
        bias, nullptr,
        nullptr, gMhi, gMlo, 1);

    // GEMM2: out = mid[8192,4096] @ wo[4096,1024] + hidden -> fp32
    gemm_mma<<<dim3(DMODEL / 128, N_NODES / 128), 256, SMEM_DYN>>>(
        gMhi, gMlo, FINT, FINT,
        gWhi, gWlo, DMODEL,
        nullptr, hidden,
        out, nullptr, nullptr, 2);
}

// round 5
// speedup vs baseline: 3.8740x; 1.0952x over previous
#include <cuda_runtime.h>
#include <cuda_bf16.h>
#include <cstdint>
#include <math.h>

#define N_NODES 8192
#define DMODEL 1024
#define FINT 4096
#define KTOT 3072
#define NEDGE 262144
#define NKEY (2 * N_NODES)
#define LN_EPS 1e-6f

// ---------------- PTX helpers (sm_80-era: valid on base compute_103) ---------
__device__ __forceinline__ uint32_t smem_u32(const void* p) {
    uint32_t a;
    asm("{ .reg .u64 t; cvta.to.shared.u64 t, %1; cvt.u32.u64 %0, t; }" : "=r"(a) : "l"(p));
    return a;
}
#define CP16(dst, src) asm volatile("cp.async.cg.shared.global [%0], [%1], 16;" :: "r"(dst), "l"(src))
#define CP_COMMIT()    asm volatile("cp.async.commit_group;" ::: "memory")
#define CP_WAIT1()     asm volatile("cp.async.wait_group 1;" ::: "memory")

__device__ __forceinline__ void ldsm4(uint32_t* r, uint32_t a) {
    asm volatile("ldmatrix.sync.aligned.m8n8.x4.shared.b16 {%0,%1,%2,%3}, [%4];"
                 : "=r"(r[0]), "=r"(r[1]), "=r"(r[2]), "=r"(r[3]) : "r"(a));
}
__device__ __forceinline__ void ldsm4t(uint32_t* r, uint32_t a) {
    asm volatile("ldmatrix.sync.aligned.m8n8.x4.trans.shared.b16 {%0,%1,%2,%3}, [%4];"
                 : "=r"(r[0]), "=r"(r[1]), "=r"(r[2]), "=r"(r[3]) : "r"(a));
}
__device__ __forceinline__ void mma16816(float* d, const uint32_t* a, const uint32_t* b) {
    asm volatile("mma.sync.aligned.m16n8k16.row.col.f32.bf16.bf16.f32 "
                 "{%0,%1,%2,%3}, {%4,%5,%6,%7}, {%8,%9}, {%0,%1,%2,%3};"
                 : "+f"(d[0]), "+f"(d[1]), "+f"(d[2]), "+f"(d[3])
                 : "r"(a[0]), "r"(a[1]), "r"(a[2]), "r"(a[3]), "r"(b[0]), "r"(b[1]));
}

// ---------------- scratch ----------------------------------------------------
__device__ float g_x[(size_t)N_NODES * DMODEL];
__device__ __nv_bfloat16 g_Ahi[(size_t)N_NODES * KTOT];
__device__ __nv_bfloat16 g_Alo[(size_t)N_NODES * KTOT];
__device__ __nv_bfloat16 g_Bhi[(size_t)KTOT * FINT];
__device__ __nv_bfloat16 g_Blo[(size_t)KTOT * FINT];
__device__ __nv_bfloat16 g_Whi[(size_t)FINT * DMODEL];
__device__ __nv_bfloat16 g_Wlo[(size_t)FINT * DMODEL];
__device__ __nv_bfloat16 g_Mhi[(size_t)N_NODES * FINT];
__device__ __nv_bfloat16 g_Mlo[(size_t)N_NODES * FINT];
__device__ int g_cnt[NKEY];
__device__ int g_off[NKEY];
__device__ int g_cur[NKEY];
__device__ int g_srcbuf[NEDGE];

// ---------------- helpers ------------------------------------------------------
__device__ __forceinline__ void split2(float x0, float x1, ushort2& hv, ushort2& lv) {
    __nv_bfloat16 h0 = __float2bfloat16(x0);
    __nv_bfloat16 h1 = __float2bfloat16(x1);
    __nv_bfloat16 l0 = __float2bfloat16(x0 - __bfloat162float(h0));
    __nv_bfloat16 l1 = __float2bfloat16(x1 - __bfloat162float(h1));
    hv.x = *(unsigned short*)&h0; hv.y = *(unsigned short*)&h1;
    lv.x = *(unsigned short*)&l0; lv.y = *(unsigned short*)&l1;
}
__device__ __forceinline__ void split4(const float4& v, ushort4& hv, ushort4& lv) {
    ushort2 h01, l01, h23, l23;
    split2(v.x, v.y, h01, l01);
    split2(v.z, v.w, h23, l23);
    hv.x = h01.x; hv.y = h01.y; hv.z = h23.x; hv.w = h23.y;
    lv.x = l01.x; lv.y = l01.y; lv.z = l23.x; lv.w = l23.y;
}

// ---------------- pipeline kernels ---------------------------------------------
__global__ void zero_cnt_kernel() {
    int i = blockIdx.x * blockDim.x + threadIdx.x;
    if (i < NKEY) g_cnt[i] = 0;
}

__global__ __launch_bounds__(256) void ln_kernel(const float* __restrict__ hs,
                                                 const float* __restrict__ gamma,
                                                 const float* __restrict__ beta) {
    int n = blockIdx.x;
    int t = threadIdx.x;
    const float4 v = ((const float4*)(hs + (size_t)n * DMODEL))[t];
    float s  = v.x + v.y + v.z + v.w;
    float sq = v.x * v.x + v.y * v.y + v.z * v.z + v.w * v.w;
    __shared__ float red[16];
    for (int o = 16; o > 0; o >>= 1) {
        s  += __shfl_down_sync(0xffffffff, s,  o);
        sq += __shfl_down_sync(0xffffffff, sq, o);
    }
    int wid = t >> 5, lid = t & 31;
    if (lid == 0) { red[wid] = s; red[8 + wid] = sq; }
    __syncthreads();
    if (wid == 0) {
        s  = (lid < 8) ? red[lid]     : 0.f;
        sq = (lid < 8) ? red[8 + lid] : 0.f;
        for (int o = 4; o > 0; o >>= 1) {
            s  += __shfl_down_sync(0xffffffff, s,  o);
            sq += __shfl_down_sync(0xffffffff, sq, o);
        }
        if (lid == 0) { red[0] = s; red[1] = sq; }
    }
    __syncthreads();
    float mean = red[0] * (1.f / DMODEL);
    float var  = red[1] * (1.f / DMODEL) - mean * mean;
    float rstd = rsqrtf(var + LN_EPS);
    const float4 g = ((const float4*)gamma)[t];
    const float4 b = ((const float4*)beta)[t];
    float4 o;
    o.x = (v.x - mean) * rstd * g.x + b.x;
    o.y = (v.y - mean) * rstd * g.y + b.y;
    o.z = (v.z - mean) * rstd * g.z + b.z;
    o.w = (v.w - mean) * rstd * g.w + b.w;
    *(float4*)&g_x[(size_t)n * DMODEL + t * 4] = o;
    ushort4 hv, lv;
    split4(o, hv, lv);
    size_t a = ((size_t)n * KTOT + 2048) / 4 + t;
    ((ushort4*)g_Ahi)[a] = hv;
    ((ushort4*)g_Alo)[a] = lv;
}

__global__ void count_kernel(const int* __restrict__ ei, const int* __restrict__ et) {
    int e = blockIdx.x * blockDim.x + threadIdx.x;
    if (e < NEDGE) atomicAdd(&g_cnt[et[e] * N_NODES + ei[NEDGE + e]], 1);
}

__global__ __launch_bounds__(1024) void scan_kernel() {
    int tid = threadIdx.x;
    int base = tid * 16;
    int loc[16];
    int s = 0;
    #pragma unroll
    for (int i = 0; i < 16; i++) { loc[i] = s; s += g_cnt[base + i]; }
    __shared__ int ps[1024];
    int mine = s;
    ps[tid] = s;
    __syncthreads();
    for (int off = 1; off < 1024; off <<= 1) {
        int v = (tid >= off) ? ps[tid - off] : 0;
        __syncthreads();
        ps[tid] += v;
        __syncthreads();
    }
    int ex = ps[tid] - mine;
    #pragma unroll
    for (int i = 0; i < 16; i++) {
        int o = ex + loc[i];
        g_off[base + i] = o;
        g_cur[base + i] = o;
    }
}

__global__ void bucket_kernel(const int* __restrict__ ei, const int* __restrict__ et) {
    int e = blockIdx.x * blockDim.x + threadIdx.x;
    if (e < NEDGE) {
        int key = et[e] * N_NODES + ei[NEDGE + e];
        int pos = atomicAdd(&g_cur[key], 1);
        g_srcbuf[pos] = ei[e];
    }
}

__global__ __launch_bounds__(256) void gather_kernel() {
    int key = blockIdx.x;
    int node = key & (N_NODES - 1);
    int r = key >> 13;
    int off = g_off[key];
    int cnt = g_cnt[key];
    int c = threadIdx.x * 4;

    float4 acc = make_float4(0.f, 0.f, 0.f, 0.f);
    int i = 0;
    for (; i + 2 <= cnt; i += 2) {
        int s0 = g_srcbuf[off + i];
        int s1 = g_srcbuf[off + i + 1];
        float4 v0 = *(const float4*)&g_x[(size_t)s0 * DMODEL + c];
        float4 v1 = *(const float4*)&g_x[(size_t)s1 * DMODEL + c];
        acc.x += v0.x + v1.x;
        acc.y += v0.y + v1.y;
        acc.z += v0.z + v1.z;
        acc.w += v0.w + v1.w;
    }
    if (i < cnt) {
        int s0 = g_srcbuf[off + i];
        float4 v0 = *(const float4*)&g_x[(size_t)s0 * DMODEL + c];
        acc.x += v0.x; acc.y += v0.y; acc.z += v0.z; acc.w += v0.w;
    }
    float sc = 1.f / (float)max(cnt, 1);
    acc.x *= sc; acc.y *= sc; acc.z *= sc; acc.w *= sc;
    ushort4 hv, lv;
    split4(acc, hv, lv);
    size_t a = ((size_t)node * KTOT + (size_t)r * 1024 + c) >> 2;
    ((ushort4*)g_Ahi)[a] = hv;
    ((ushort4*)g_Alo)[a] = lv;
}

__global__ void split_kernel(const float* __restrict__ src,
                             __nv_bfloat16* __restrict__ hi,
                             __nv_bfloat16* __restrict__ lo, size_t n4) {
    size_t i = (size_t)blockIdx.x * blockDim.x + threadIdx.x;
    for (; i < n4; i += (size_t)gridDim.x * blockDim.x) {
        float4 v = ((const float4*)src)[i];
        ushort4 hv, lv;
        split4(v, hv, lv);
        ((ushort4*)hi)[i] = hv;
        ((ushort4*)lo)[i] = lv;
    }
}

// ---------------- mma.sync split-bf16 GEMM, CTA 128x256, warp 64x64 ------------
// stage: Ahi 16K | Alo 16K | Bhi 32K | Blo 32K = 96K; 2 stages = 192K
#define STAGE_BYTES 98304
#define OFF_ALO 16384
#define OFF_BHI 32768
#define OFF_BLO 65536
#define SMEM_DYN (2 * STAGE_BYTES)

__device__ __forceinline__ uint32_t a_off(int row, int q) {
    return (uint32_t)(row * 128 + ((q ^ (row & 7)) << 4));
}
// B row = k (0..63), q = 16B chunk within 512B row (0..31)
__device__ __forceinline__ uint32_t b_off(int row, int q) {
    return (uint32_t)(row * 512 + (((q & 24) | ((q & 7) ^ (row & 7))) << 4));
}

__global__ __launch_bounds__(256, 1) void gemm_mma(
    const __nv_bfloat16* __restrict__ Ahi, const __nv_bfloat16* __restrict__ Alo,
    int ldA, int K,
    const __nv_bfloat16* __restrict__ Bhi, const __nv_bfloat16* __restrict__ Blo,
    int ldB,
    const float* __restrict__ bias, const float* __restrict__ residual,
    float* __restrict__ outF,
    __nv_bfloat16* __restrict__ outHi, __nv_bfloat16* __restrict__ outLo,
    int mode)
{
    extern __shared__ __align__(1024) char smem[];
    const uint32_t sb = smem_u32(smem);
    const int tid = threadIdx.x, wid = tid >> 5, lane = tid & 31;
    const int rowBase = blockIdx.y * 128;
    const int nBase   = blockIdx.x * 256;
    const int warp_m = (wid >> 2) * 64;   // 0 | 64
    const int warp_n = (wid & 3) * 64;    // 0 | 64 | 128 | 192
    const int lr = lane & 15, lc = lane >> 4;
    const int nchunk = K >> 6;

    float acc[4][8][4];
    #pragma unroll
    for (int i = 0; i < 4; i++)
        #pragma unroll
        for (int j = 0; j < 8; j++)
            #pragma unroll
            for (int k = 0; k < 4; k++) acc[i][j][k] = 0.f;

    auto load_chunk = [&](int c, int s) {
        const uint32_t sbase = sb + s * STAGE_BYTES;
        const int kb = c * 64;
        #pragma unroll
        for (int i = 0; i < 4; i++) {
            int v = tid + i * 256;
            int row = v >> 3, q = v & 7;
            uint32_t so = sbase + a_off(row, q);
            size_t g = (size_t)(rowBase + row) * ldA + kb + q * 8;
            CP16(so, Ahi + g);
            CP16(so + OFF_ALO, Alo + g);
        }
        #pragma unroll
        for (int i = 0; i < 8; i++) {
            int v = tid + i * 256;
            int row = v >> 5, q = v & 31;
            uint32_t so = sbase + OFF_BHI + b_off(row, q);
            size_t g = (size_t)(kb + row) * ldB + nBase + q * 8;
            CP16(so, Bhi + g);
            CP16(so + (OFF_BLO - OFF_BHI), Blo + g);
        }
    };

    load_chunk(0, 0); CP_COMMIT();
    load_chunk(1, 1); CP_COMMIT();

    for (int c = 0; c < nchunk; c++) {
        CP_WAIT1();
        __syncthreads();
        const uint32_t base = sb + (c & 1) * STAGE_BYTES;
        #pragma unroll
        for (int ks = 0; ks < 4; ks++) {
            uint32_t ah[4][4], al[4][4];
            #pragma unroll
            for (int mi = 0; mi < 4; mi++) {
                int row = warp_m + mi * 16 + lr;
                int q = ks * 2 + lc;
                uint32_t addr = base + a_off(row, q);
                ldsm4(ah[mi], addr);
                ldsm4(al[mi], addr + OFF_ALO);
            }
            #pragma unroll
            for (int np = 0; np < 4; np++) {
                int row = ks * 16 + lr;
                int q = (warp_n >> 3) + np * 2 + lc;
                uint32_t addr = base + OFF_BHI + b_off(row, q);
                uint32_t th[4], tl[4];
                ldsm4t(th, addr);
                ldsm4t(tl, addr + (OFF_BLO - OFF_BHI));
                uint32_t bh0[2] = { th[0], th[1] }, bh1[2] = { th[2], th[3] };
                uint32_t bl0[2] = { tl[0], tl[1] }, bl1[2] = { tl[2], tl[3] };
                #pragma unroll
                for (int mi = 0; mi < 4; mi++) {
                    mma16816(acc[mi][np * 2], ah[mi], bh0);
                    mma16816(acc[mi][np * 2], ah[mi], bl0);
                    mma16816(acc[mi][np * 2], al[mi], bh0);
                    mma16816(acc[mi][np * 2 + 1], ah[mi], bh1);
                    mma16816(acc[mi][np * 2 + 1], ah[mi], bl1);
                    mma16816(acc[mi][np * 2 + 1], al[mi], bh1);
                }
            }
        }
        __syncthreads();
        if (c + 2 < nchunk) load_chunk(c + 2, c & 1);
        CP_COMMIT();
    }

    #pragma unroll
    for (int mi = 0; mi < 4; mi++) {
        #pragma unroll
        for (int ni = 0; ni < 8; ni++) {
            int r0 = rowBase + warp_m + mi * 16 + (lane >> 2);
            int col = nBase + warp_n + ni * 8 + (lane & 3) * 2;
            #pragma unroll
            for (int h = 0; h < 2; h++) {
                int row = r0 + h * 8;
                float x0 = acc[mi][ni][h * 2 + 0];
                float x1 = acc[mi][ni][h * 2 + 1];
                size_t go = (size_t)row * ldB + col;
                if (mode == 1) {
                    x0 = fmaxf(x0 + bias[col], 0.f);
                    x1 = fmaxf(x1 + bias[col + 1], 0.f);
                    ushort2 hv, lv;
                    split2(x0, x1, hv, lv);
                    *(ushort2*)&outHi[go] = hv;
                    *(ushort2*)&outLo[go] = lv;
                } else {
                    float2 res = *(const float2*)&residual[go];
                    float2 y = { x0 + res.x, x1 + res.y };
                    *(float2*)&outF[go] = y;
                }
            }
        }
    }
}

// ---------------- launch -------------------------------------------------------
extern "C" void kernel_launch(void* const* d_in, const int* in_sizes, int n_in,
                              void* d_out, int out_size) {
    const float* hidden = (const float*)d_in[0];
    const float* weight = (const float*)d_in[1];
    const float* root   = (const float*)d_in[2];
    const float* bias   = (const float*)d_in[3];
    const float* wo     = (const float*)d_in[4];
    const float* gamma  = (const float*)d_in[5];
    const float* beta   = (const float*)d_in[6];
    const int*   ei     = (const int*)d_in[7];
    const int*   et     = (const int*)d_in[8];
    float* out = (float*)d_out;

    __nv_bfloat16 *gAhi, *gAlo, *gBhi, *gBlo, *gWhi, *gWlo, *gMhi, *gMlo;
    cudaGetSymbolAddress((void**)&gAhi, g_Ahi);
    cudaGetSymbolAddress((void**)&gAlo, g_Alo);
    cudaGetSymbolAddress((void**)&gBhi, g_Bhi);
    cudaGetSymbolAddress((void**)&gBlo, g_Blo);
    cudaGetSymbolAddress((void**)&gWhi, g_Whi);
    cudaGetSymbolAddress((void**)&gWlo, g_Wlo);
    cudaGetSymbolAddress((void**)&gMhi, g_Mhi);
    cudaGetSymbolAddress((void**)&gMlo, g_Mlo);

    cudaFuncSetAttribute(gemm_mma, cudaFuncAttributeMaxDynamicSharedMemorySize, SMEM_DYN);

    zero_cnt_kernel<<<NKEY / 256, 256>>>();
    ln_kernel<<<N_NODES, 256>>>(hidden, gamma, beta);
    count_kernel<<<NEDGE / 256, 256>>>(ei, et);
    scan_kernel<<<1, 1024>>>();
    bucket_kernel<<<NEDGE / 256, 256>>>(ei, et);
    gather_kernel<<<NKEY, 256>>>();

    split_kernel<<<2048, 256>>>(weight, gBhi, gBlo, (size_t)2048 * FINT / 4);
    split_kernel<<<1024, 256>>>(root, gBhi + (size_t)2048 * FINT, gBlo + (size_t)2048 * FINT,
                                (size_t)1024 * FINT / 4);
    split_kernel<<<1024, 256>>>(wo, gWhi, gWlo, (size_t)FINT * DMODEL / 4);

    // GEMM1: mid = relu(A[8192,3072] @ [weight;root][3072,4096] + bias) -> bf16 hi/lo
    gemm_mma<<<dim3(FINT / 256, N_NODES / 128), 256, SMEM_DYN>>>(
        gAhi, gAlo, KTOT, KTOT,
        gBhi, gBlo, FINT,
        bias, nullptr,
        nullptr, gMhi, gMlo, 1);

    // GEMM2: out = mid[8192,4096] @ wo[4096,1024] + hidden -> fp32
    gemm_mma<<<dim3(DMODEL / 256, N_NODES / 128), 256, SMEM_DYN>>>(
        gMhi, gMlo, FINT, FINT,
        gWhi, gWlo, DMODEL,
        nullptr, hidden,
        out, nullptr, nullptr, 2);
}

// round 6
// speedup vs baseline: 3.9236x; 1.0128x over previous
#include <cuda_runtime.h>
#include <cuda_bf16.h>
#include <cstdint>
#include <math.h>

#define N_NODES 8192
#define DMODEL 1024
#define FINT 4096
#define KTOT 3072
#define NEDGE 262144
#define NKEY (2 * N_NODES)
#define LN_EPS 1e-6f

// ---------------- PTX helpers (sm_80-era: valid on base compute_103) ---------
__device__ __forceinline__ uint32_t smem_u32(const void* p) {
    uint32_t a;
    asm("{ .reg .u64 t; cvta.to.shared.u64 t, %1; cvt.u32.u64 %0, t; }" : "=r"(a) : "l"(p));
    return a;
}
#define CP16(dst, src) asm volatile("cp.async.cg.shared.global [%0], [%1], 16;" :: "r"(dst), "l"(src))
#define CP_COMMIT()    asm volatile("cp.async.commit_group;" ::: "memory")
#define CP_WAIT1()     asm volatile("cp.async.wait_group 1;" ::: "memory")

__device__ __forceinline__ void ldsm4(uint32_t* r, uint32_t a) {
    asm volatile("ldmatrix.sync.aligned.m8n8.x4.shared.b16 {%0,%1,%2,%3}, [%4];"
                 : "=r"(r[0]), "=r"(r[1]), "=r"(r[2]), "=r"(r[3]) : "r"(a));
}
__device__ __forceinline__ void ldsm4t(uint32_t* r, uint32_t a) {
    asm volatile("ldmatrix.sync.aligned.m8n8.x4.trans.shared.b16 {%0,%1,%2,%3}, [%4];"
                 : "=r"(r[0]), "=r"(r[1]), "=r"(r[2]), "=r"(r[3]) : "r"(a));
}
__device__ __forceinline__ void mma16816(float* d, const uint32_t* a, const uint32_t* b) {
    asm volatile("mma.sync.aligned.m16n8k16.row.col.f32.bf16.bf16.f32 "
                 "{%0,%1,%2,%3}, {%4,%5,%6,%7}, {%8,%9}, {%0,%1,%2,%3};"
                 : "+f"(d[0]), "+f"(d[1]), "+f"(d[2]), "+f"(d[3])
                 : "r"(a[0]), "r"(a[1]), "r"(a[2]), "r"(a[3]), "r"(b[0]), "r"(b[1]));
}

// ---------------- scratch ----------------------------------------------------
__device__ float g_x[(size_t)N_NODES * DMODEL];
__device__ __nv_bfloat16 g_Ahi[(size_t)N_NODES * KTOT];
__device__ __nv_bfloat16 g_Alo[(size_t)N_NODES * KTOT];
__device__ __nv_bfloat16 g_Bhi[(size_t)KTOT * FINT];
__device__ __nv_bfloat16 g_Blo[(size_t)KTOT * FINT];
__device__ __nv_bfloat16 g_Whi[(size_t)FINT * DMODEL];
__device__ __nv_bfloat16 g_Wlo[(size_t)FINT * DMODEL];
__device__ __nv_bfloat16 g_Mhi[(size_t)N_NODES * FINT];
__device__ __nv_bfloat16 g_Mlo[(size_t)N_NODES * FINT];
__device__ int g_cnt[NKEY];
__device__ int g_off[NKEY];
__device__ int g_cur[NKEY];
__device__ int g_srcbuf[NEDGE];

// ---------------- helpers ------------------------------------------------------
__device__ __forceinline__ void split2(float x0, float x1, ushort2& hv, ushort2& lv) {
    __nv_bfloat16 h0 = __float2bfloat16(x0);
    __nv_bfloat16 h1 = __float2bfloat16(x1);
    __nv_bfloat16 l0 = __float2bfloat16(x0 - __bfloat162float(h0));
    __nv_bfloat16 l1 = __float2bfloat16(x1 - __bfloat162float(h1));
    hv.x = *(unsigned short*)&h0; hv.y = *(unsigned short*)&h1;
    lv.x = *(unsigned short*)&l0; lv.y = *(unsigned short*)&l1;
}
__device__ __forceinline__ void split4(const float4& v, ushort4& hv, ushort4& lv) {
    ushort2 h01, l01, h23, l23;
    split2(v.x, v.y, h01, l01);
    split2(v.z, v.w, h23, l23);
    hv.x = h01.x; hv.y = h01.y; hv.z = h23.x; hv.w = h23.y;
    lv.x = l01.x; lv.y = l01.y; lv.z = l23.x; lv.w = l23.y;
}

// ---------------- pipeline kernels ---------------------------------------------
__global__ void zero_cnt_kernel() {
    int i = blockIdx.x * blockDim.x + threadIdx.x;
    if (i < NKEY) g_cnt[i] = 0;
}

__global__ __launch_bounds__(256) void ln_kernel(const float* __restrict__ hs,
                                                 const float* __restrict__ gamma,
                                                 const float* __restrict__ beta) {
    int n = blockIdx.x;
    int t = threadIdx.x;
    const float4 v = ((const float4*)(hs + (size_t)n * DMODEL))[t];
    float s  = v.x + v.y + v.z + v.w;
    float sq = v.x * v.x + v.y * v.y + v.z * v.z + v.w * v.w;
    __shared__ float red[16];
    for (int o = 16; o > 0; o >>= 1) {
        s  += __shfl_down_sync(0xffffffff, s,  o);
        sq += __shfl_down_sync(0xffffffff, sq, o);
    }
    int wid = t >> 5, lid = t & 31;
    if (lid == 0) { red[wid] = s; red[8 + wid] = sq; }
    __syncthreads();
    if (wid == 0) {
        s  = (lid < 8) ? red[lid]     : 0.f;
        sq = (lid < 8) ? red[8 + lid] : 0.f;
        for (int o = 4; o > 0; o >>= 1) {
            s  += __shfl_down_sync(0xffffffff, s,  o);
            sq += __shfl_down_sync(0xffffffff, sq, o);
        }
        if (lid == 0) { red[0] = s; red[1] = sq; }
    }
    __syncthreads();
    float mean = red[0] * (1.f / DMODEL);
    float var  = red[1] * (1.f / DMODEL) - mean * mean;
    float rstd = rsqrtf(var + LN_EPS);
    const float4 g = ((const float4*)gamma)[t];
    const float4 b = ((const float4*)beta)[t];
    float4 o;
    o.x = (v.x - mean) * rstd * g.x + b.x;
    o.y = (v.y - mean) * rstd * g.y + b.y;
    o.z = (v.z - mean) * rstd * g.z + b.z;
    o.w = (v.w - mean) * rstd * g.w + b.w;
    *(float4*)&g_x[(size_t)n * DMODEL + t * 4] = o;
    ushort4 hv, lv;
    split4(o, hv, lv);
    size_t a = ((size_t)n * KTOT + 2048) / 4 + t;
    ((ushort4*)g_Ahi)[a] = hv;
    ((ushort4*)g_Alo)[a] = lv;
}

__global__ void count_kernel(const int* __restrict__ ei, const int* __restrict__ et) {
    int e = blockIdx.x * blockDim.x + threadIdx.x;
    if (e < NEDGE) atomicAdd(&g_cnt[et[e] * N_NODES + ei[NEDGE + e]], 1);
}

// two-level shfl scan over 16384 counts (1024 threads x 16)
__global__ __launch_bounds__(1024) void scan_kernel() {
    int tid = threadIdx.x;
    int lane = tid & 31, wid = tid >> 5;
    int base = tid * 16;
    int loc[16];
    int s = 0;
    #pragma unroll
    for (int i = 0; i < 16; i++) { loc[i] = s; s += g_cnt[base + i]; }
    // warp inclusive scan of per-thread totals
    int inc = s;
    #pragma unroll
    for (int o = 1; o < 32; o <<= 1) {
        int v = __shfl_up_sync(0xffffffff, inc, o);
        if (lane >= o) inc += v;
    }
    __shared__ int wtot[32];
    if (lane == 31) wtot[wid] = inc;
    __syncthreads();
    if (wid == 0) {
        int w = wtot[lane];
        int wi = w;
        #pragma unroll
        for (int o = 1; o < 32; o <<= 1) {
            int v = __shfl_up_sync(0xffffffff, wi, o);
            if (lane >= o) wi += v;
        }
        wtot[lane] = wi - w;  // exclusive
    }
    __syncthreads();
    int ex = wtot[wid] + (inc - s);  // exclusive prefix for this thread
    #pragma unroll
    for (int i = 0; i < 16; i++) {
        int o = ex + loc[i];
        g_off[base + i] = o;
        g_cur[base + i] = o;
    }
}

__global__ void bucket_kernel(const int* __restrict__ ei, const int* __restrict__ et) {
    int e = blockIdx.x * blockDim.x + threadIdx.x;
    if (e < NEDGE) {
        int key = et[e] * N_NODES + ei[NEDGE + e];
        int pos = atomicAdd(&g_cur[key], 1);
        g_srcbuf[pos] = ei[e];
    }
}

__global__ __launch_bounds__(256) void gather_kernel() {
    int key = blockIdx.x;
    int node = key & (N_NODES - 1);
    int r = key >> 13;
    int off = g_off[key];
    int cnt = g_cnt[key];
    int c = threadIdx.x * 4;

    float4 acc = make_float4(0.f, 0.f, 0.f, 0.f);
    int i = 0;
    for (; i + 4 <= cnt; i += 4) {
        int s0 = g_srcbuf[off + i];
        int s1 = g_srcbuf[off + i + 1];
        int s2 = g_srcbuf[off + i + 2];
        int s3 = g_srcbuf[off + i + 3];
        float4 v0 = *(const float4*)&g_x[(size_t)s0 * DMODEL + c];
        float4 v1 = *(const float4*)&g_x[(size_t)s1 * DMODEL + c];
        float4 v2 = *(const float4*)&g_x[(size_t)s2 * DMODEL + c];
        float4 v3 = *(const float4*)&g_x[(size_t)s3 * DMODEL + c];
        acc.x += (v0.x + v1.x) + (v2.x + v3.x);
        acc.y += (v0.y + v1.y) + (v2.y + v3.y);
        acc.z += (v0.z + v1.z) + (v2.z + v3.z);
        acc.w += (v0.w + v1.w) + (v2.w + v3.w);
    }
    for (; i < cnt; i++) {
        int s0 = g_srcbuf[off + i];
        float4 v0 = *(const float4*)&g_x[(size_t)s0 * DMODEL + c];
        acc.x += v0.x; acc.y += v0.y; acc.z += v0.z; acc.w += v0.w;
    }
    float sc = 1.f / (float)max(cnt, 1);
    acc.x *= sc; acc.y *= sc; acc.z *= sc; acc.w *= sc;
    ushort4 hv, lv;
    split4(acc, hv, lv);
    size_t a = ((size_t)node * KTOT + (size_t)r * 1024 + c) >> 2;
    ((ushort4*)g_Ahi)[a] = hv;
    ((ushort4*)g_Alo)[a] = lv;
}

__global__ void split_kernel(const float* __restrict__ src,
                             __nv_bfloat16* __restrict__ hi,
                             __nv_bfloat16* __restrict__ lo, size_t n4) {
    size_t i = (size_t)blockIdx.x * blockDim.x + threadIdx.x;
    for (; i < n4; i += (size_t)gridDim.x * blockDim.x) {
        float4 v = ((const float4*)src)[i];
        ushort4 hv, lv;
        split4(v, hv, lv);
        ((ushort4*)hi)[i] = hv;
        ((ushort4*)lo)[i] = lv;
    }
}

// ---------------- mma.sync split-bf16 GEMM, CTA 128x256, warp 64x64 ------------
#define STAGE_BYTES 98304
#define OFF_ALO 16384
#define OFF_BHI 32768
#define OFF_BLO 65536
#define SMEM_DYN (2 * STAGE_BYTES)
#define EPIPITCH 264   // ushorts per staged row (conflict-free)

__device__ __forceinline__ uint32_t a_off(int row, int q) {
    return (uint32_t)(row * 128 + ((q ^ (row & 7)) << 4));
}
__device__ __forceinline__ uint32_t b_off(int row, int q) {
    return (uint32_t)(row * 512 + (((q & 24) | ((q & 7) ^ (row & 7))) << 4));
}

__global__ __launch_bounds__(256, 1) void gemm_mma(
    const __nv_bfloat16* __restrict__ Ahi, const __nv_bfloat16* __restrict__ Alo,
    int ldA, int K,
    const __nv_bfloat16* __restrict__ Bhi, const __nv_bfloat16* __restrict__ Blo,
    int ldB,
    const float* __restrict__ bias, const float* __restrict__ residual,
    float* __restrict__ outF,
    __nv_bfloat16* __restrict__ outHi, __nv_bfloat16* __restrict__ outLo,
    int mode)
{
    extern __shared__ __align__(1024) char smem[];
    const uint32_t sb = smem_u32(smem);
    const int tid = threadIdx.x, wid = tid >> 5, lane = tid & 31;
    const int rowBase = blockIdx.y * 128;
    const int nBase   = blockIdx.x * 256;
    const int warp_m = (wid >> 2) * 64;
    const int warp_n = (wid & 3) * 64;
    const int lr = lane & 15, lc = lane >> 4;
    const int nchunk = K >> 6;

    float acc[4][8][4];
    #pragma unroll
    for (int i = 0; i < 4; i++)
        #pragma unroll
        for (int j = 0; j < 8; j++)
            #pragma unroll
            for (int k = 0; k < 4; k++) acc[i][j][k] = 0.f;

    auto load_chunk = [&](int c, int s) {
        const uint32_t sbase = sb + s * STAGE_BYTES;
        const int kb = c * 64;
        #pragma unroll
        for (int i = 0; i < 4; i++) {
            int v = tid + i * 256;
            int row = v >> 3, q = v & 7;
            uint32_t so = sbase + a_off(row, q);
            size_t g = (size_t)(rowBase + row) * ldA + kb + q * 8;
            CP16(so, Ahi + g);
            CP16(so + OFF_ALO, Alo + g);
        }
        #pragma unroll
        for (int i = 0; i < 8; i++) {
            int v = tid + i * 256;
            int row = v >> 5, q = v & 31;
            uint32_t so = sbase + OFF_BHI + b_off(row, q);
            size_t g = (size_t)(kb + row) * ldB + nBase + q * 8;
            CP16(so, Bhi + g);
            CP16(so + (OFF_BLO - OFF_BHI), Blo + g);
        }
    };

    load_chunk(0, 0); CP_COMMIT();
    load_chunk(1, 1); CP_COMMIT();

    for (int c = 0; c < nchunk; c++) {
        CP_WAIT1();
        __syncthreads();
        const uint32_t base = sb + (c & 1) * STAGE_BYTES;
        #pragma unroll
        for (int ks = 0; ks < 4; ks++) {
            uint32_t ah[4][4], al[4][4];
            #pragma unroll
            for (int mi = 0; mi < 4; mi++) {
                int row = warp_m + mi * 16 + lr;
                int q = ks * 2 + lc;
                uint32_t addr = base + a_off(row, q);
                ldsm4(ah[mi], addr);
                ldsm4(al[mi], addr + OFF_ALO);
            }
            #pragma unroll
            for (int np = 0; np < 4; np++) {
                int row = ks * 16 + lr;
                int q = (warp_n >> 3) + np * 2 + lc;
                uint32_t addr = base + OFF_BHI + b_off(row, q);
                uint32_t th[4], tl[4];
                ldsm4t(th, addr);
                ldsm4t(tl, addr + (OFF_BLO - OFF_BHI));
                uint32_t bh0[2] = { th[0], th[1] }, bh1[2] = { th[2], th[3] };
                uint32_t bl0[2] = { tl[0], tl[1] }, bl1[2] = { tl[2], tl[3] };
                #pragma unroll
                for (int mi = 0; mi < 4; mi++) {
                    mma16816(acc[mi][np * 2], ah[mi], bh0);
                    mma16816(acc[mi][np * 2], ah[mi], bl0);
                    mma16816(acc[mi][np * 2], al[mi], bh0);
                    mma16816(acc[mi][np * 2 + 1], ah[mi], bh1);
                    mma16816(acc[mi][np * 2 + 1], ah[mi], bl1);
                    mma16816(acc[mi][np * 2 + 1], al[mi], bh1);
                }
            }
        }
        __syncthreads();
        if (c + 2 < nchunk) load_chunk(c + 2, c & 1);
        CP_COMMIT();
    }

    if (mode == 1) {
        // stage hi/lo tiles through smem, then fully-coalesced 16B stores
        unsigned short* stH = (unsigned short*)smem;
        unsigned short* stL = stH + 128 * EPIPITCH;
        #pragma unroll
        for (int mi = 0; mi < 4; mi++) {
            #pragma unroll
            for (int ni = 0; ni < 8; ni++) {
                int rl0 = warp_m + mi * 16 + (lane >> 2);
                int cl  = warp_n + ni * 8 + (lane & 3) * 2;
                #pragma unroll
                for (int h = 0; h < 2; h++) {
                    int rl = rl0 + h * 8;
                    float x0 = acc[mi][ni][h * 2 + 0];
                    float x1 = acc[mi][ni][h * 2 + 1];
                    int gc = nBase + cl;
                    x0 = fmaxf(x0 + bias[gc], 0.f);
                    x1 = fmaxf(x1 + bias[gc + 1], 0.f);
                    ushort2 hv, lv;
                    split2(x0, x1, hv, lv);
                    *(ushort2*)&stH[rl * EPIPITCH + cl] = hv;
                    *(ushort2*)&stL[rl * EPIPITCH + cl] = lv;
                }
            }
        }
        __syncthreads();
        #pragma unroll
        for (int i = 0; i < 16; i++) {
            int idx = tid + i * 256;       // 4096 chunks of 16B
            int row = idx >> 5, ch = idx & 31;
            uint4 vh = *(uint4*)&stH[row * EPIPITCH + ch * 8];
            uint4 vl = *(uint4*)&stL[row * EPIPITCH + ch * 8];
            size_t go = (size_t)(rowBase + row) * ldB + nBase + ch * 8;
            *(uint4*)&outHi[go] = vh;
            *(uint4*)&outLo[go] = vl;
        }
    } else {
        #pragma unroll
        for (int mi = 0; mi < 4; mi++) {
            #pragma unroll
            for (int ni = 0; ni < 8; ni++) {
                int r0 = rowBase + warp_m + mi * 16 + (lane >> 2);
                int col = nBase + warp_n + ni * 8 + (lane & 3) * 2;
                #pragma unroll
                for (int h = 0; h < 2; h++) {
                    int row = r0 + h * 8;
                    float x0 = acc[mi][ni][h * 2 + 0];
                    float x1 = acc[mi][ni][h * 2 + 1];
                    size_t go = (size_t)row * ldB + col;
                    float2 res = *(const float2*)&residual[go];
                    float2 y = { x0 + res.x, x1 + res.y };
                    *(float2*)&outF[go] = y;
                }
            }
        }
    }
}

// ---------------- launch -------------------------------------------------------
extern "C" void kernel_launch(void* const* d_in, const int* in_sizes, int n_in,
                              void* d_out, int out_size) {
    const float* hidden = (const float*)d_in[0];
    const float* weight = (const float*)d_in[1];
    const float* root   = (const float*)d_in[2];
    const float* bias   = (const float*)d_in[3];
    const float* wo     = (const float*)d_in[4];
    const float* gamma  = (const float*)d_in[5];
    const float* beta   = (const float*)d_in[6];
    const int*   ei     = (const int*)d_in[7];
    const int*   et     = (const int*)d_in[8];
    float* out = (float*)d_out;

    __nv_bfloat16 *gAhi, *gAlo, *gBhi, *gBlo, *gWhi, *gWlo, *gMhi, *gMlo;
    cudaGetSymbolAddress((void**)&gAhi, g_Ahi);
    cudaGetSymbolAddress((void**)&gAlo, g_Alo);
    cudaGetSymbolAddress((void**)&gBhi, g_Bhi);
    cudaGetSymbolAddress((void**)&gBlo, g_Blo);
    cudaGetSymbolAddress((void**)&gWhi, g_Whi);
    cudaGetSymbolAddress((void**)&gWlo, g_Wlo);
    cudaGetSymbolAddress((void**)&gMhi, g_Mhi);
    cudaGetSymbolAddress((void**)&gMlo, g_Mlo);

    cudaFuncSetAttribute(gemm_mma, cudaFuncAttributeMaxDynamicSharedMemorySize, SMEM_DYN);

    zero_cnt_kernel<<<NKEY / 256, 256>>>();
    ln_kernel<<<N_NODES, 256>>>(hidden, gamma, beta);
    count_kernel<<<NEDGE / 256, 256>>>(ei, et);
    scan_kernel<<<1, 1024>>>();
    bucket_kernel<<<NEDGE / 256, 256>>>(ei, et);
    gather_kernel<<<NKEY, 256>>>();

    split_kernel<<<2048, 256>>>(weight, gBhi, gBlo, (size_t)2048 * FINT / 4);
    split_kernel<<<1024, 256>>>(root, gBhi + (size_t)2048 * FINT, gBlo + (size_t)2048 * FINT,
                                (size_t)1024 * FINT / 4);
    split_kernel<<<1024, 256>>>(wo, gWhi, gWlo, (size_t)FINT * DMODEL / 4);

    // GEMM1: mid = relu(A[8192,3072] @ [weight;root][3072,4096] + bias) -> bf16 hi/lo
    gemm_mma<<<dim3(FINT / 256, N_NODES / 128), 256, SMEM_DYN>>>(
        gAhi, gAlo, KTOT, KTOT,
        gBhi, gBlo, FINT,
        bias, nullptr,
        nullptr, gMhi, gMlo, 1);

    // GEMM2: out = mid[8192,4096] @ wo[4096,1024] + hidden -> fp32
    gemm_mma<<<dim3(DMODEL / 256, N_NODES / 128), 256, SMEM_DYN>>>(
        gMhi, gMlo, FINT, FINT,
        gWhi, gWlo, DMODEL,
        nullptr, hidden,
        out, nullptr, nullptr, 2);
}